// round 1
// baseline (speedup 1.0000x reference)
#include <cuda_runtime.h>
#include <math.h>

#define Vv 34004
#define Ee 300
#define Hh 512
#define Bb 64
#define Tt 512
#define G4H 2048

// ---------------- scratch (device globals; no runtime allocation) ----------------
__device__ float g_xzf[67108864];   // [T][B][4H]  fw pre-activations (268 MB)
__device__ float g_xzb[67108864];   // [T][B][4H]  bw pre-activations, already in scan order
__device__ float g_h[2 * Bb * Hh];  // double h state: [dir][B][H]
__device__ unsigned g_bar;          // grid barrier counter (monotonic within a launch)

// =================================================================================
// Phase A: xz[t,b,:] = emb[tokens[b,t]] @ W + bias   (both directions)
// Tiled FP32 GEMM, M = B*T (m = t*B + b), N = 4096 (fw cols then bw cols), K = 300.
// BM=128, BN=64, BK=16, 256 threads, 8x4 micro-tile.
// =================================================================================
__global__ __launch_bounds__(256) void gemm_in(
    const int* __restrict__ tokens, const float* __restrict__ emb,
    const float* __restrict__ W_fw, const float* __restrict__ b_fw,
    const float* __restrict__ W_bw, const float* __restrict__ b_bw)
{
    __shared__ __align__(16) float a_s[16][128];  // [kk][r] (transposed)
    __shared__ __align__(16) float w_s[16][64];
    __shared__ int tok_s[128];

    const int tid = threadIdx.x;
    const int m0 = blockIdx.x * 128;
    const int nb = blockIdx.y;

    if (tid < 128) {
        int m = m0 + tid;
        int t = m >> 6, b = m & 63;
        tok_s[tid] = tokens[b * Tt + t];
    }

    const bool bw = (nb >= 32);
    const float* __restrict__ W    = bw ? W_bw : W_fw;
    const float* __restrict__ bias = bw ? b_bw : b_fw;
    const int n0 = (bw ? nb - 32 : nb) * 64;

    const int ry = tid >> 4;          // 0..15 -> rows ry*8 .. +8
    const int cx = tid & 15;          // 0..15 -> cols cx*4 .. +4

    float acc[8][4];
#pragma unroll
    for (int i = 0; i < 8; i++)
#pragma unroll
        for (int j = 0; j < 4; j++) acc[i][j] = 0.f;

    __syncthreads();

    for (int k0 = 0; k0 < Ee; k0 += 16) {
        // A tile: each thread loads 8 floats of one emb row (2x float4)
        {
            int r = tid >> 1, kk0 = (tid & 1) * 8;
            const float* src = emb + (size_t)tok_s[r] * Ee + k0 + kk0;
#pragma unroll
            for (int u = 0; u < 8; u += 4) {
                int k = k0 + kk0 + u;
                float4 v = make_float4(0.f, 0.f, 0.f, 0.f);
                if (k + 3 < Ee) v = *(const float4*)(src + u);   // E%4==0, k%4==0
                a_s[kk0 + u + 0][r] = v.x;
                a_s[kk0 + u + 1][r] = v.y;
                a_s[kk0 + u + 2][r] = v.z;
                a_s[kk0 + u + 3][r] = v.w;
            }
        }
        // W tile: each thread one float4
        {
            int kk = tid >> 4, nn = (tid & 15) * 4;
            int k = k0 + kk;
            float4 v = make_float4(0.f, 0.f, 0.f, 0.f);
            if (k < Ee) v = *(const float4*)(W + (size_t)k * G4H + n0 + nn);
            *(float4*)&w_s[kk][nn] = v;
        }
        __syncthreads();

#pragma unroll
        for (int kk = 0; kk < 16; kk++) {
            float4 av0 = *(const float4*)&a_s[kk][ry * 8];
            float4 av1 = *(const float4*)&a_s[kk][ry * 8 + 4];
            float4 wv  = *(const float4*)&w_s[kk][cx * 4];
            float a[8] = {av0.x, av0.y, av0.z, av0.w, av1.x, av1.y, av1.z, av1.w};
            float w[4] = {wv.x, wv.y, wv.z, wv.w};
#pragma unroll
            for (int i = 0; i < 8; i++)
#pragma unroll
                for (int j = 0; j < 4; j++) acc[i][j] += a[i] * w[j];
        }
        __syncthreads();
    }

    float4 bv = *(const float4*)(bias + n0 + cx * 4);
#pragma unroll
    for (int i = 0; i < 8; i++) {
        int m = m0 + ry * 8 + i;
        int t = m >> 6, b = m & 63;
        size_t row = bw ? ((size_t)(Tt - 1 - t) * Bb + b) : (size_t)m;
        float* dst = (bw ? g_xzb : g_xzf) + row * G4H + n0 + cx * 4;
        float4 o;
        o.x = acc[i][0] + bv.x;
        o.y = acc[i][1] + bv.y;
        o.z = acc[i][2] + bv.z;
        o.w = acc[i][3] + bv.w;
        *(float4*)dst = o;
    }
}

// =================================================================================
// init: reset barrier counter, seed h state from h0 inputs (runs every launch)
// =================================================================================
__global__ void init_kernel(const float* __restrict__ h0_fw,
                            const float* __restrict__ h0_bw)
{
    int i = blockIdx.x * blockDim.x + threadIdx.x;
    if (i == 0) g_bar = 0u;
    if (i < Bb * Hh) {
        g_h[i]           = h0_fw[i];
        g_h[Bb * Hh + i] = h0_bw[i];
    }
}

// =================================================================================
// Phase B: persistent bidirectional LSTM scan.
// 128 CTAs: dir = blk>>6, jblk = blk&63 -> 8 hidden units -> 32 z-columns.
// SMEM: U slice [512][32], h stage [64][516], z tile [32][66], c state [512].
// One L2-atomic grid barrier per step.
// =================================================================================
#define HS 516
#define ZS 66
#define SCAN_SMEM_FLOATS (512 * 32 + 64 * HS + 32 * ZS + 512)
#define SCAN_SMEM_BYTES  (SCAN_SMEM_FLOATS * 4)

__global__ __launch_bounds__(256, 1) void lstm_scan(
    const float* __restrict__ U_fw, const float* __restrict__ U_bw,
    const float* __restrict__ c0_fw, const float* __restrict__ c0_bw,
    float* __restrict__ out, float* __restrict__ hT, float* __restrict__ cT)
{
    extern __shared__ __align__(16) float sm[];
    float* U_s = sm;                    // [512][32]
    float* h_s = U_s + 512 * 32;        // [64][HS]
    float* z_s = h_s + 64 * HS;         // [32][ZS] (col-major: [c][b])
    float* c_s = z_s + 32 * ZS;         // [512]  (b*8 + jj)

    const int tid  = threadIdx.x;
    const int dir  = blockIdx.x >> 6;
    const int jblk = blockIdx.x & 63;
    const int j0   = jblk * 8;

    const float* __restrict__ U  = dir ? U_bw : U_fw;
    const float* __restrict__ c0 = dir ? c0_bw : c0_fw;
    const float* __restrict__ xz = dir ? g_xzb : g_xzf;
    float* hbuf = g_h + dir * Bb * Hh;

    // persistent U slice: U_s[k][c], c -> gate=c>>3, jj=c&7
    for (int i = tid; i < 512 * 32; i += 256) {
        int k = i >> 5, c = i & 31;
        U_s[i] = U[(size_t)k * G4H + (c >> 3) * Hh + j0 + (c & 7)];
    }
    // c state
    for (int i = tid; i < 512; i += 256)
        c_s[i] = c0[(i >> 3) * Hh + j0 + (i & 7)];

    const int ry  = tid >> 4;           // 16 row-groups of 4 batches
    const int cx  = tid & 15;           // 16 col-pairs
    const int b0  = ry * 4;
    const int c0i = cx * 2;
    const int gate    = c0i >> 3;
    const int colbase = gate * Hh + j0 + (c0i & 7);

    for (int step = 0; step < Tt; step++) {
        // stage h (L2, bypass L1 for cross-SM coherence)
        const float4* hsrc = (const float4*)hbuf;
        for (int i = tid; i < (Bb * Hh) / 4; i += 256) {
            float4 v = __ldcg(hsrc + i);
            int b = i >> 7;
            int k = (i & 127) * 4;
            *(float4*)&h_s[b * HS + k] = v;
        }
        __syncthreads();

        // acc = xz[step] tile
        float acc[4][2];
        {
            const float* row = xz + ((size_t)step * Bb + b0) * G4H + colbase;
#pragma unroll
            for (int i = 0; i < 4; i++) {
                float2 v = *(const float2*)(row + (size_t)i * G4H);
                acc[i][0] = v.x;
                acc[i][1] = v.y;
            }
        }

        // z += h @ U  (K=512, unroll 4)
#pragma unroll 2
        for (int k = 0; k < Hh; k += 4) {
            float4 hv0 = *(const float4*)&h_s[(b0 + 0) * HS + k];
            float4 hv1 = *(const float4*)&h_s[(b0 + 1) * HS + k];
            float4 hv2 = *(const float4*)&h_s[(b0 + 2) * HS + k];
            float4 hv3 = *(const float4*)&h_s[(b0 + 3) * HS + k];
#pragma unroll
            for (int u = 0; u < 4; u++) {
                float2 uv = *(const float2*)&U_s[(k + u) * 32 + c0i];
                float h0v = (u == 0) ? hv0.x : (u == 1) ? hv0.y : (u == 2) ? hv0.z : hv0.w;
                float h1v = (u == 0) ? hv1.x : (u == 1) ? hv1.y : (u == 2) ? hv1.z : hv1.w;
                float h2v = (u == 0) ? hv2.x : (u == 1) ? hv2.y : (u == 2) ? hv2.z : hv2.w;
                float h3v = (u == 0) ? hv3.x : (u == 1) ? hv3.y : (u == 2) ? hv3.z : hv3.w;
                acc[0][0] += h0v * uv.x; acc[0][1] += h0v * uv.y;
                acc[1][0] += h1v * uv.x; acc[1][1] += h1v * uv.y;
                acc[2][0] += h2v * uv.x; acc[2][1] += h2v * uv.y;
                acc[3][0] += h3v * uv.x; acc[3][1] += h3v * uv.y;
            }
        }

        // publish z tile to smem (transposed [c][b])
#pragma unroll
        for (int i = 0; i < 4; i++) {
            z_s[(c0i + 0) * ZS + b0 + i] = acc[i][0];
            z_s[(c0i + 1) * ZS + b0 + i] = acc[i][1];
        }
        __syncthreads();

        // gates: 512 (b,jj) pairs, 2 per thread
#pragma unroll
        for (int pp = 0; pp < 2; pp++) {
            int p  = tid + pp * 256;
            int b  = p >> 3, jj = p & 7;
            float zi = z_s[(0  + jj) * ZS + b];
            float zf = z_s[(8  + jj) * ZS + b];
            float zg = z_s[(16 + jj) * ZS + b];
            float zo = z_s[(24 + jj) * ZS + b];
            float cold = c_s[p];
            float ig = 1.f / (1.f + expf(-zi));
            float fg = 1.f / (1.f + expf(-zf));
            float gg = tanhf(zg);
            float og = 1.f / (1.f + expf(-zo));
            float cn = fg * cold + ig * gg;
            float hn = og * tanhf(cn);
            c_s[p] = cn;
            int j = j0 + jj;
            __stcg(&hbuf[b * Hh + j], hn);
            int tout = dir ? (Tt - 1 - step) : step;
            out[((size_t)b * Tt + tout) * (2 * Hh) + dir * Hh + j] = hn;
            if (step == Tt - 1) {
                hT[b * 2 * Hh + dir * Hh + j] = hn;
                cT[b * 2 * Hh + dir * Hh + j] = cn;
            }
        }

        // grid barrier: release writes, arrive, spin on L2 counter
        __threadfence();
        __syncthreads();
        if (tid == 0) {
            atomicAdd(&g_bar, 1u);
            unsigned target = (unsigned)(step + 1) * gridDim.x;
            while (atomicAdd(&g_bar, 0u) < target) __nanosleep(64);
        }
        __syncthreads();
    }
}

// =================================================================================
extern "C" void kernel_launch(void* const* d_in, const int* in_sizes, int n_in,
                              void* d_out, int out_size)
{
    const int*   tokens = (const int*)  d_in[0];
    const float* h0_fw  = (const float*)d_in[1];
    const float* c0_fw  = (const float*)d_in[2];
    const float* h0_bw  = (const float*)d_in[3];
    const float* c0_bw  = (const float*)d_in[4];
    const float* emb    = (const float*)d_in[5];
    const float* W_fw   = (const float*)d_in[6];
    const float* U_fw   = (const float*)d_in[7];
    const float* b_fw   = (const float*)d_in[8];
    const float* W_bw   = (const float*)d_in[9];
    const float* U_bw   = (const float*)d_in[10];
    const float* b_bw   = (const float*)d_in[11];

    float* out = (float*)d_out;                       // [B,T,2H]
    float* hT  = out + (size_t)Bb * Tt * 2 * Hh;      // [B,2H]
    float* cT  = hT + (size_t)Bb * 2 * Hh;            // [B,2H]

    gemm_in<<<dim3(256, 64), 256>>>(tokens, emb, W_fw, b_fw, W_bw, b_bw);
    init_kernel<<<128, 256>>>(h0_fw, h0_bw);

    cudaFuncSetAttribute(lstm_scan, cudaFuncAttributeMaxDynamicSharedMemorySize,
                         SCAN_SMEM_BYTES);
    lstm_scan<<<128, 256, SCAN_SMEM_BYTES>>>(U_fw, U_bw, c0_fw, c0_bw, out, hT, cT);
}

// round 2
// speedup vs baseline: 1.6446x; 1.6446x over previous
#include <cuda_runtime.h>
#include <math.h>

#define Vv 34004
#define Ee 300
#define Hh 512
#define Bb 64
#define Tt 512
#define G4H 2048
#define BH (Bb * Hh)

// ---------------- scratch (device globals; no runtime allocation) ----------------
__device__ float g_xzf[67108864];      // [T][B][4H]  fw pre-activations
__device__ float g_xzb[67108864];      // [T][B][4H]  bw pre-activations (scan order)
__device__ float g_h[2 * 2 * BH];      // ping-pong: [buf][dir][B][H]
__device__ unsigned g_bar;             // grid barrier counter (monotonic per launch)

// =================================================================================
// Phase A: xz[t,b,:] = emb[tokens[b,t]] @ W + bias   (both directions)
// Tiled FP32 GEMM, M = B*T, N = 4096 (fw||bw), K = 300.
// BM=128, BN=64, BK=16, 256 threads, 8x4 micro-tile, double-buffered smem.
// =================================================================================
__global__ __launch_bounds__(256) void gemm_in(
    const int* __restrict__ tokens, const float* __restrict__ emb,
    const float* __restrict__ W_fw, const float* __restrict__ b_fw,
    const float* __restrict__ W_bw, const float* __restrict__ b_bw)
{
    __shared__ __align__(16) float a_s[2][16][128];   // [buf][kk][r]
    __shared__ __align__(16) float w_s[2][16][64];    // [buf][kk][n]
    __shared__ int tok_s[128];

    const int tid = threadIdx.x;
    const int m0 = blockIdx.x * 128;
    const int nb = blockIdx.y;

    if (tid < 128) {
        int m = m0 + tid;
        int t = m >> 6, b = m & 63;
        tok_s[tid] = tokens[b * Tt + t];
    }

    const bool bw = (nb >= 32);
    const float* __restrict__ W    = bw ? W_bw : W_fw;
    const float* __restrict__ bias = bw ? b_bw : b_fw;
    const int n0 = (bw ? nb - 32 : nb) * 64;

    const int ry = tid >> 4;
    const int cx = tid & 15;

    // load-lane roles
    const int ar  = tid >> 1;          // emb row 0..127
    const int ak0 = (tid & 1) * 8;     // k sub-offset 0 or 8
    const int wk  = tid >> 4;          // W k-row 0..15
    const int wn  = (tid & 15) * 4;    // W col 0..60

    float acc[8][4];
#pragma unroll
    for (int i = 0; i < 8; i++)
#pragma unroll
        for (int j = 0; j < 4; j++) acc[i][j] = 0.f;

    __syncthreads();   // tok_s ready

    float4 areg0, areg1, wreg;
    const int NT = 19;  // ceil(300/16)

    // prologue: global -> regs -> smem[0]
    {
        const float* src = emb + (size_t)tok_s[ar] * Ee + ak0;
        areg0 = (ak0 + 0 < Ee) ? *(const float4*)(src + 0) : make_float4(0, 0, 0, 0);
        areg1 = (ak0 + 4 < Ee) ? *(const float4*)(src + 4) : make_float4(0, 0, 0, 0);
        wreg  = (wk < Ee) ? *(const float4*)(W + (size_t)wk * G4H + n0 + wn)
                          : make_float4(0, 0, 0, 0);
        a_s[0][ak0 + 0][ar] = areg0.x; a_s[0][ak0 + 1][ar] = areg0.y;
        a_s[0][ak0 + 2][ar] = areg0.z; a_s[0][ak0 + 3][ar] = areg0.w;
        a_s[0][ak0 + 4][ar] = areg1.x; a_s[0][ak0 + 5][ar] = areg1.y;
        a_s[0][ak0 + 6][ar] = areg1.z; a_s[0][ak0 + 7][ar] = areg1.w;
        *(float4*)&w_s[0][wk][wn] = wreg;
    }
    __syncthreads();

    for (int kt = 0; kt < NT; kt++) {
        const int cur = kt & 1, nxt = cur ^ 1;

        // prefetch next tile into regs (overlaps with FFMAs below)
        if (kt + 1 < NT) {
            int k0 = (kt + 1) * 16;
            const float* src = emb + (size_t)tok_s[ar] * Ee + k0 + ak0;
            int ka = k0 + ak0;
            areg0 = (ka + 0 < Ee) ? *(const float4*)(src + 0) : make_float4(0, 0, 0, 0);
            areg1 = (ka + 4 < Ee) ? *(const float4*)(src + 4) : make_float4(0, 0, 0, 0);
            int kw = k0 + wk;
            wreg = (kw < Ee) ? *(const float4*)(W + (size_t)kw * G4H + n0 + wn)
                             : make_float4(0, 0, 0, 0);
        }

#pragma unroll
        for (int kk = 0; kk < 16; kk++) {
            float4 av0 = *(const float4*)&a_s[cur][kk][ry * 8];
            float4 av1 = *(const float4*)&a_s[cur][kk][ry * 8 + 4];
            float4 wv  = *(const float4*)&w_s[cur][kk][cx * 4];
            float a[8] = {av0.x, av0.y, av0.z, av0.w, av1.x, av1.y, av1.z, av1.w};
            float w[4] = {wv.x, wv.y, wv.z, wv.w};
#pragma unroll
            for (int i = 0; i < 8; i++)
#pragma unroll
                for (int j = 0; j < 4; j++) acc[i][j] += a[i] * w[j];
        }

        if (kt + 1 < NT) {
            a_s[nxt][ak0 + 0][ar] = areg0.x; a_s[nxt][ak0 + 1][ar] = areg0.y;
            a_s[nxt][ak0 + 2][ar] = areg0.z; a_s[nxt][ak0 + 3][ar] = areg0.w;
            a_s[nxt][ak0 + 4][ar] = areg1.x; a_s[nxt][ak0 + 5][ar] = areg1.y;
            a_s[nxt][ak0 + 6][ar] = areg1.z; a_s[nxt][ak0 + 7][ar] = areg1.w;
            *(float4*)&w_s[nxt][wk][wn] = wreg;
        }
        __syncthreads();
    }

    float4 bv = *(const float4*)(bias + n0 + cx * 4);
#pragma unroll
    for (int i = 0; i < 8; i++) {
        int m = m0 + ry * 8 + i;
        int t = m >> 6, b = m & 63;
        size_t row = bw ? ((size_t)(Tt - 1 - t) * Bb + b) : (size_t)m;
        float* dst = (bw ? g_xzb : g_xzf) + row * G4H + n0 + cx * 4;
        float4 o;
        o.x = acc[i][0] + bv.x;
        o.y = acc[i][1] + bv.y;
        o.z = acc[i][2] + bv.z;
        o.w = acc[i][3] + bv.w;
        *(float4*)dst = o;
    }
}

// =================================================================================
// init: reset barrier counter, seed h state buf0 from h0 inputs (every launch)
// =================================================================================
__global__ void init_kernel(const float* __restrict__ h0_fw,
                            const float* __restrict__ h0_bw)
{
    int i = blockIdx.x * blockDim.x + threadIdx.x;
    if (i == 0) g_bar = 0u;
    if (i < BH) {
        g_h[i]      = h0_fw[i];   // buf0, dir0
        g_h[BH + i] = h0_bw[i];   // buf0, dir1
    }
}

__device__ __forceinline__ float sigmoidf_fast(float x) {
    return __fdividef(1.f, 1.f + __expf(-x));
}

// =================================================================================
// Phase B: persistent bidirectional LSTM scan.
// 128 CTAs: dir = blk>>6, jblk = blk&63 -> 8 hidden units -> 32 z-columns.
// SMEM: U packed [256][64] (2k x 2c float4 groups), h stage [64][516],
//       z tile [32][66], c state [512]. Ping-pong h in L2, acquire-poll barrier.
// =================================================================================
#define HS 516
#define ZS 66
#define SCAN_SMEM_FLOATS (512 * 32 + 64 * HS + 32 * ZS + 512)
#define SCAN_SMEM_BYTES  (SCAN_SMEM_FLOATS * 4)

__global__ __launch_bounds__(256, 1) void lstm_scan(
    const float* __restrict__ U_fw, const float* __restrict__ U_bw,
    const float* __restrict__ c0_fw, const float* __restrict__ c0_bw,
    float* __restrict__ out, float* __restrict__ hT, float* __restrict__ cT)
{
    extern __shared__ __align__(16) float sm[];
    float* U_s = sm;                    // packed [k/2][32*2]: (2k x 2c) float4 cells
    float* h_s = U_s + 512 * 32;        // [64][HS]
    float* z_s = h_s + 64 * HS;         // [32][ZS] col-major [c][b]
    float* c_s = z_s + 32 * ZS;         // [512] (b*8 + jj)

    const int tid  = threadIdx.x;
    const int dir  = blockIdx.x >> 6;
    const int jblk = blockIdx.x & 63;
    const int j0   = jblk * 8;

    const float* __restrict__ U  = dir ? U_bw : U_fw;
    const float* __restrict__ c0 = dir ? c0_bw : c0_fw;
    const float* __restrict__ xz = dir ? g_xzb : g_xzf;

    // persistent U slice, packed: cell m covers k={2m,2m+1}, addr layout:
    // U_s[m*64 + c*2 + (k&1)]  ->  float4 at (m*64 + c0i*2) = {U[2m][c],U[2m+1][c],U[2m][c+1],U[2m+1][c+1]}
    for (int i = tid; i < 512 * 32; i += 256) {
        int k = i >> 5, c = i & 31;
        U_s[(k >> 1) * 64 + c * 2 + (k & 1)] =
            U[(size_t)k * G4H + (c >> 3) * Hh + j0 + (c & 7)];
    }
    for (int i = tid; i < 512; i += 256)
        c_s[i] = c0[(i >> 3) * Hh + j0 + (i & 7)];

    const int ry  = tid >> 4;
    const int cx  = tid & 15;
    const int b0  = ry * 4;
    const int c0i = cx * 2;
    const int gate    = c0i >> 3;
    const int colbase = gate * Hh + j0 + (c0i & 7);

    for (int step = 0; step < Tt; step++) {
        const float* hbuf_r = g_h + (((step) & 1) * 2 + dir) * BH;
        float*       hbuf_w = g_h + (((step + 1) & 1) * 2 + dir) * BH;

        // issue xz DRAM loads FIRST (577-cyc latency overlaps h staging)
        float acc[4][2];
        {
            const float* row = xz + ((size_t)step * Bb + b0) * G4H + colbase;
#pragma unroll
            for (int i = 0; i < 4; i++) {
                float2 v = __ldcs((const float2*)(row + (size_t)i * G4H));
                acc[i][0] = v.x;
                acc[i][1] = v.y;
            }
        }

        // stage h from L2 (bypass L1 for cross-SM coherence)
        {
            const float4* hsrc = (const float4*)hbuf_r;
#pragma unroll 4
            for (int i = tid; i < BH / 4; i += 256) {
                float4 v = __ldcg(hsrc + i);
                int b = i >> 7;
                int k = (i & 127) * 4;
                *(float4*)&h_s[b * HS + k] = v;
            }
        }
        __syncthreads();

        // z += h @ U  (K=512): 4 h LDS.128 + 2 U LDS.128 + 32 FFMA per 4-k
#pragma unroll 4
        for (int k = 0; k < Hh; k += 4) {
            float4 hv0 = *(const float4*)&h_s[(b0 + 0) * HS + k];
            float4 hv1 = *(const float4*)&h_s[(b0 + 1) * HS + k];
            float4 hv2 = *(const float4*)&h_s[(b0 + 2) * HS + k];
            float4 hv3 = *(const float4*)&h_s[(b0 + 3) * HS + k];
            float4 ua = *(const float4*)&U_s[(k >> 1) * 64 + c0i * 2];        // k,k+1
            float4 ub = *(const float4*)&U_s[((k >> 1) + 1) * 64 + c0i * 2];  // k+2,k+3

            acc[0][0] += hv0.x * ua.x; acc[0][1] += hv0.x * ua.z;
            acc[1][0] += hv1.x * ua.x; acc[1][1] += hv1.x * ua.z;
            acc[2][0] += hv2.x * ua.x; acc[2][1] += hv2.x * ua.z;
            acc[3][0] += hv3.x * ua.x; acc[3][1] += hv3.x * ua.z;

            acc[0][0] += hv0.y * ua.y; acc[0][1] += hv0.y * ua.w;
            acc[1][0] += hv1.y * ua.y; acc[1][1] += hv1.y * ua.w;
            acc[2][0] += hv2.y * ua.y; acc[2][1] += hv2.y * ua.w;
            acc[3][0] += hv3.y * ua.y; acc[3][1] += hv3.y * ua.w;

            acc[0][0] += hv0.z * ub.x; acc[0][1] += hv0.z * ub.z;
            acc[1][0] += hv1.z * ub.x; acc[1][1] += hv1.z * ub.z;
            acc[2][0] += hv2.z * ub.x; acc[2][1] += hv2.z * ub.z;
            acc[3][0] += hv3.z * ub.x; acc[3][1] += hv3.z * ub.z;

            acc[0][0] += hv0.w * ub.y; acc[0][1] += hv0.w * ub.w;
            acc[1][0] += hv1.w * ub.y; acc[1][1] += hv1.w * ub.w;
            acc[2][0] += hv2.w * ub.y; acc[2][1] += hv2.w * ub.w;
            acc[3][0] += hv3.w * ub.y; acc[3][1] += hv3.w * ub.w;
        }

        // publish z tile (transposed [c][b])
#pragma unroll
        for (int i = 0; i < 4; i++) {
            z_s[(c0i + 0) * ZS + b0 + i] = acc[i][0];
            z_s[(c0i + 1) * ZS + b0 + i] = acc[i][1];
        }
        __syncthreads();

        // gates: 512 (b,jj) pairs, 2 per thread
#pragma unroll
        for (int pp = 0; pp < 2; pp++) {
            int p  = tid + pp * 256;
            int b  = p >> 3, jj = p & 7;
            float zi = z_s[(0  + jj) * ZS + b];
            float zf = z_s[(8  + jj) * ZS + b];
            float zg = z_s[(16 + jj) * ZS + b];
            float zo = z_s[(24 + jj) * ZS + b];
            float cold = c_s[p];
            float ig = sigmoidf_fast(zi);
            float fg = sigmoidf_fast(zf);
            float gg = tanhf(zg);
            float og = sigmoidf_fast(zo);
            float cn = fg * cold + ig * gg;
            float hn = og * tanhf(cn);
            c_s[p] = cn;
            int j = j0 + jj;
            __stcg(&hbuf_w[b * Hh + j], hn);
            int tout = dir ? (Tt - 1 - step) : step;
            out[((size_t)b * Tt + tout) * (2 * Hh) + dir * Hh + j] = hn;
            if (step == Tt - 1) {
                hT[b * 2 * Hh + dir * Hh + j] = hn;
                cT[b * 2 * Hh + dir * Hh + j] = cn;
            }
        }

        // grid barrier: fence, arrive (atomic), acquire-poll (plain L2 load)
        __threadfence();
        __syncthreads();
        if (tid == 0) {
            atomicAdd(&g_bar, 1u);
            unsigned target = (unsigned)(step + 1) * gridDim.x;
            unsigned v;
            do {
                asm volatile("ld.acquire.gpu.global.u32 %0, [%1];"
                             : "=r"(v) : "l"(&g_bar) : "memory");
                if (v >= target) break;
                __nanosleep(32);
            } while (true);
        }
        __syncthreads();
    }
}

// =================================================================================
extern "C" void kernel_launch(void* const* d_in, const int* in_sizes, int n_in,
                              void* d_out, int out_size)
{
    const int*   tokens = (const int*)  d_in[0];
    const float* h0_fw  = (const float*)d_in[1];
    const float* c0_fw  = (const float*)d_in[2];
    const float* h0_bw  = (const float*)d_in[3];
    const float* c0_bw  = (const float*)d_in[4];
    const float* emb    = (const float*)d_in[5];
    const float* W_fw   = (const float*)d_in[6];
    const float* U_fw   = (const float*)d_in[7];
    const float* b_fw   = (const float*)d_in[8];
    const float* W_bw   = (const float*)d_in[9];
    const float* U_bw   = (const float*)d_in[10];
    const float* b_bw   = (const float*)d_in[11];

    float* out = (float*)d_out;                       // [B,T,2H]
    float* hT  = out + (size_t)Bb * Tt * 2 * Hh;      // [B,2H]
    float* cT  = hT + (size_t)Bb * 2 * Hh;            // [B,2H]

    gemm_in<<<dim3(256, 64), 256>>>(tokens, emb, W_fw, b_fw, W_bw, b_bw);
    init_kernel<<<128, 256>>>(h0_fw, h0_bw);

    cudaFuncSetAttribute(lstm_scan, cudaFuncAttributeMaxDynamicSharedMemorySize,
                         SCAN_SMEM_BYTES);
    lstm_scan<<<128, 256, SCAN_SMEM_BYTES>>>(U_fw, U_bw, c0_fw, c0_bw, out, hT, cT);
}